// round 6
// baseline (speedup 1.0000x reference)
#include <cuda_runtime.h>
#include <math.h>
#include <float.h>

#define HIDDEN 5120
#define NH 40
#define HD 128
#define MAXL 2048
#define QL 8
#define CHUNK 256
#define NCHUNK (MAXL / CHUNK)
#define QK_SCALE 0.08838834764831845f  // 1/sqrt(128)
#define C4 (HIDDEN / 4)                // 1280 float4 per row
#define ROWS 4
#define NITER (C4 / 256)               // 5

// packed f32x2 FMA for attn kernel
#define FMAX2(acc, a, b) \
    asm("fma.rn.f32x2 %0, %1, %2, %0;" : "+l"(acc) : "l"(a), "l"(b))

__device__ __forceinline__ float x2lo(unsigned long long v) {
    return __uint_as_float((unsigned)(v & 0xffffffffu));
}
__device__ __forceinline__ float x2hi(unsigned long long v) {
    return __uint_as_float((unsigned)(v >> 32));
}
__device__ __forceinline__ float x2sum(unsigned long long v) {
    return x2lo(v) + x2hi(v);
}
__device__ __forceinline__ unsigned long long f32dup(float p) {
    unsigned b = __float_as_uint(p);
    return ((unsigned long long)b << 32) | b;
}

__device__ __forceinline__ unsigned smem_u32(const void* p) {
    unsigned a;
    asm("{ .reg .u64 t; cvta.to.shared.u64 t, %1; cvt.u32.u64 %0, t; }"
        : "=r"(a) : "l"(p));
    return a;
}
template <int N>
__device__ __forceinline__ void cp_wait() {
    asm volatile("cp.async.wait_group %0;" :: "n"(N));
}

// ---------------- device scratch (no allocs allowed) ----------------
__device__ float g_q[NH * QL * HD];                    // [h][q][d], pre-scaled
__device__ float g_k[NH * QL * HD];                    // new K rows  [h][q][d]
__device__ float g_v[NH * QL * HD];                    // new V rows  [h][q][d]
__device__ float g_opart[NH * QL * NCHUNK * HD];       // [h][q][chunk][d]
__device__ float g_m[NH * QL * NCHUNK];                // chunk max
__device__ float g_l[NH * QL * NCHUNK];                // chunk expsum
__device__ float g_ctx[QL * HIDDEN];                   // attention out [q][h*128+d]

// ---------------------------------------------------------------
// GEMV, M=8: Y[q][r] = dot(X[q], W[r]).
// 4 rows/block, 8-q scalar register tile. W streamed via cp.async.cg
// (L2-only) into a 3-stage private smem slot per thread: load issue
// decoupled from consumption, no barrier in the main loop.
// X via __ldg (L1-resident across CTAs).
// Dynamic smem exactly 48 KB; reduction scratch aliased onto it
// (all stages consumed before reuse). No static smem -> launch fits
// the 48 KB default without opt-in.
// mode 0: W_pack -> g_q/g_k/g_v.  mode 1: W_o, X=g_ctx -> Y.
// ---------------------------------------------------------------
__global__ void __launch_bounds__(256, 3) gemv8_kernel(
    const float* __restrict__ Xin, const float* __restrict__ W,
    float* __restrict__ Y, int mode)
{
    extern __shared__ float4 sW[];     // [stage][row][tid], 48 KB

    const float4* __restrict__ X4 =
        reinterpret_cast<const float4*>((mode == 1) ? g_ctx : Xin);

    int tid = threadIdx.x;
    long r0 = (long)blockIdx.x * ROWS;
    const float* __restrict__ Wp = W + (size_t)r0 * HIDDEN + tid * 4;

    unsigned sbase = smem_u32(sW) + tid * 16;   // this thread's slot

    float acc[ROWS][QL];
#pragma unroll
    for (int r = 0; r < ROWS; r++)
#pragma unroll
        for (int q = 0; q < QL; q++) acc[r][q] = 0.0f;

    // issue one group: ROWS cp.async of 16B for iteration `it` into stage `s`
#define GEMV_ISSUE(it, s)                                                   \
    {                                                                       \
        const float* g = Wp + (it) * 1024;                                  \
        _Pragma("unroll")                                                   \
        for (int r = 0; r < ROWS; r++) {                                    \
            unsigned sa = sbase + (unsigned)(((s) * ROWS + r) << 12);       \
            asm volatile("cp.async.cg.shared.global [%0], [%1], 16;"        \
                         :: "r"(sa), "l"(g + (size_t)r * HIDDEN));          \
        }                                                                   \
        asm volatile("cp.async.commit_group;");                             \
    }

#define GEMV_CONSUME(it, s)                                                 \
    {                                                                       \
        float4 wv[ROWS];                                                    \
        _Pragma("unroll")                                                   \
        for (int r = 0; r < ROWS; r++) {                                    \
            unsigned sa = sbase + (unsigned)(((s) * ROWS + r) << 12);       \
            asm volatile("ld.shared.v4.f32 {%0,%1,%2,%3}, [%4];"            \
                         : "=f"(wv[r].x), "=f"(wv[r].y),                    \
                           "=f"(wv[r].z), "=f"(wv[r].w) : "r"(sa));         \
        }                                                                   \
        int c4 = tid + (it) * 256;                                          \
        _Pragma("unroll")                                                   \
        for (int q = 0; q < QL; q++) {                                      \
            float4 xv = __ldg(X4 + q * C4 + c4);                            \
            _Pragma("unroll")                                               \
            for (int r = 0; r < ROWS; r++) {                                \
                acc[r][q] = fmaf(wv[r].x, xv.x, acc[r][q]);                 \
                acc[r][q] = fmaf(wv[r].y, xv.y, acc[r][q]);                 \
                acc[r][q] = fmaf(wv[r].z, xv.z, acc[r][q]);                 \
                acc[r][q] = fmaf(wv[r].w, xv.w, acc[r][q]);                 \
            }                                                               \
        }                                                                   \
    }

    // 3-stage pipeline over NITER=5 iterations
    GEMV_ISSUE(0, 0)
    GEMV_ISSUE(1, 1)
    GEMV_ISSUE(2, 2)
    cp_wait<2>(); GEMV_CONSUME(0, 0) GEMV_ISSUE(3, 0)
    cp_wait<2>(); GEMV_CONSUME(1, 1) GEMV_ISSUE(4, 1)
    cp_wait<2>(); GEMV_CONSUME(2, 2)
    cp_wait<1>(); GEMV_CONSUME(3, 0)
    cp_wait<0>(); GEMV_CONSUME(4, 1)

    // block reduction: warp shuffle, then cross-warp via smem.
    // Reuse the first 1 KB of sW (all cp.async drained; barrier protects).
    float* sred = reinterpret_cast<float*>(sW);   // [warp][r*8+q] -> warp*32+i
    int lane = tid & 31, warp = tid >> 5;
    __syncthreads();   // everyone done consuming before scratch reuse
#pragma unroll
    for (int r = 0; r < ROWS; r++) {
#pragma unroll
        for (int q = 0; q < QL; q++) {
            float v = acc[r][q];
            v += __shfl_down_sync(0xffffffffu, v, 16);
            v += __shfl_down_sync(0xffffffffu, v, 8);
            v += __shfl_down_sync(0xffffffffu, v, 4);
            v += __shfl_down_sync(0xffffffffu, v, 2);
            v += __shfl_down_sync(0xffffffffu, v, 1);
            if (lane == 0) sred[warp * 32 + r * QL + q] = v;
        }
    }
    __syncthreads();
    if (tid < 32) {
        float v = 0.0f;
#pragma unroll
        for (int w = 0; w < 8; w++) v += sred[w * 32 + tid];
        long r = r0 + tid / QL;
        int q = tid % QL;
        if (mode == 0) {
            int sect = (int)(r / HIDDEN);      // 0=q, 1=k, 2=v
            int f = (int)(r % HIDDEN);
            int h = f / HD, d = f % HD;
            int o = (h * QL + q) * HD + d;
            if (sect == 0)      g_q[o] = v * QK_SCALE;
            else if (sect == 1) g_k[o] = v;
            else                g_v[o] = v;
        } else {
            Y[(long)q * HIDDEN + r] = v;
        }
    }
}

// ---------------------------------------------------------------
// Split-KV attention: block = (chunk of 256 keys, head). f32x2 in both
// matmul phases; probs stored pre-duplicated (p,p) in smem for PV phase.
// ---------------------------------------------------------------
__global__ void __launch_bounds__(256) attn_kernel(
    const float* __restrict__ kc, const float* __restrict__ vc,
    const float* __restrict__ mask, const int* __restrict__ ipos)
{
    int chunk = blockIdx.x;
    int h = blockIdx.y;
    int tid = threadIdx.x;
    int warp = tid >> 5, lane = tid & 31;

    __shared__ float qs[QL][HD];                    // 4 KB
    __shared__ float scf[QL][CHUNK];                // 8 KB scores
    __shared__ unsigned long long sc2[QL][CHUNK];   // 16 KB dup probs
    __shared__ float4 red[8][QL][32];               // 32 KB partial O
    __shared__ int pos[QL];
    __shared__ int sel[CHUNK];

    if (tid == 0) {
        bool is64 = (ipos[1] == 0);     // int64 little-endian high word
#pragma unroll
        for (int j = 0; j < QL; j++) pos[j] = is64 ? ipos[2 * j] : ipos[j];
    }
    for (int i = tid; i < QL * HD; i += 256) qs[0][i] = g_q[h * QL * HD + i];
    __syncthreads();

    // ---- scores: one key per thread, f32x2 pairs over d ----
    int key = chunk * CHUNK + tid;
    int s = -1;
#pragma unroll
    for (int j = 0; j < QL; j++) if (pos[j] == key) s = j;
    sel[tid] = s;

    const ulonglong2* kp = reinterpret_cast<const ulonglong2*>(
        (s >= 0) ? &g_k[(h * QL + s) * HD]
                 : &kc[((size_t)h * MAXL + key) * HD]);
    unsigned long long a2[QL];
#pragma unroll
    for (int q = 0; q < QL; q++) a2[q] = 0ull;
#pragma unroll
    for (int c = 0; c < HD / 4; c += 8) {
        ulonglong2 kv[8];
#pragma unroll
        for (int u = 0; u < 8; u++) kv[u] = __ldcg(kp + c + u);
#pragma unroll
        for (int u = 0; u < 8; u++) {
#pragma unroll
            for (int q = 0; q < QL; q++) {
                ulonglong2 qv = *reinterpret_cast<const ulonglong2*>(
                    &qs[q][(c + u) * 4]);
                FMAX2(a2[q], kv[u].x, qv.x);
                FMAX2(a2[q], kv[u].y, qv.y);
            }
        }
    }
#pragma unroll
    for (int q = 0; q < QL; q++) {
        float m = __ldcg(&mask[((size_t)h * MAXL + pos[q]) * MAXL + key]);
        scf[q][tid] = fmaxf(x2sum(a2[q]) + m, -FLT_MAX);
    }
    __syncthreads();

    // ---- softmax stats: warp q handles query q; write dup probs ----
    {
        float m = -FLT_MAX;
#pragma unroll
        for (int i = 0; i < CHUNK / 32; i++) m = fmaxf(m, scf[warp][lane + i * 32]);
#pragma unroll
        for (int o = 16; o > 0; o >>= 1) m = fmaxf(m, __shfl_xor_sync(0xffffffffu, m, o));
        float l = 0.0f;
#pragma unroll
        for (int i = 0; i < CHUNK / 32; i++) {
            float p = __expf(scf[warp][lane + i * 32] - m);
            sc2[warp][lane + i * 32] = f32dup(p);
            l += p;
        }
#pragma unroll
        for (int o = 16; o > 0; o >>= 1) l += __shfl_xor_sync(0xffffffffu, l, o);
        if (lane == 0) {
            g_m[(h * QL + warp) * NCHUNK + chunk] = m;
            g_l[(h * QL + warp) * NCHUNK + chunk] = l;
        }
    }
    __syncthreads();

    // ---- partial O = P^T V. warp w: keys w,w+8,...; lane: d-float4 ----
    unsigned long long acc[QL][2];     // 2 d-pairs per lane
#pragma unroll
    for (int q = 0; q < QL; q++) { acc[q][0] = 0ull; acc[q][1] = 0ull; }

#pragma unroll
    for (int j = 0; j < 32; j += 4) {
        ulonglong2 vv[4];
#pragma unroll
        for (int u = 0; u < 4; u++) {
            int k = warp + 8 * (j + u);
            int sv = sel[k];
            int kk = chunk * CHUNK + k;
            const ulonglong2* vp = reinterpret_cast<const ulonglong2*>(
                (sv >= 0) ? &g_v[(h * QL + sv) * HD]
                          : &vc[((size_t)h * MAXL + kk) * HD]);
            vv[u] = __ldcg(vp + lane);
        }
#pragma unroll
        for (int u = 0; u < 4; u++) {
            int k = warp + 8 * (j + u);
#pragma unroll
            for (int q = 0; q < QL; q++) {
                unsigned long long p2 = sc2[q][k];
                FMAX2(acc[q][0], p2, vv[u].x);
                FMAX2(acc[q][1], p2, vv[u].y);
            }
        }
    }
#pragma unroll
    for (int q = 0; q < QL; q++)
        red[warp][q][lane] = make_float4(x2lo(acc[q][0]), x2hi(acc[q][0]),
                                         x2lo(acc[q][1]), x2hi(acc[q][1]));
    __syncthreads();

    // reduce 8 warps: thread t handles (q, d4) = (t/32, t%32)
    {
        int q = tid >> 5, d4 = tid & 31;
        float4 o = red[0][q][d4];
#pragma unroll
        for (int w = 1; w < 8; w++) {
            float4 v = red[w][q][d4];
            o.x += v.x; o.y += v.y; o.z += v.z; o.w += v.w;
        }
        reinterpret_cast<float4*>(
            &g_opart[((h * QL + q) * NCHUNK + chunk) * HD])[d4] = o;
    }
}

// ---------------------------------------------------------------
// Combine split-KV partials (log-sum-exp merge) -> context [q][h*128+d]
// ---------------------------------------------------------------
__global__ void __launch_bounds__(HD) combine_kernel()
{
    int hq = blockIdx.x;                // h*QL + q
    int d = threadIdx.x;
    float mv[NCHUNK];
    float M = -FLT_MAX;
#pragma unroll
    for (int c = 0; c < NCHUNK; c++) {
        mv[c] = g_m[hq * NCHUNK + c];
        M = fmaxf(M, mv[c]);
    }
    float wf[NCHUNK];
    float denom = 0.0f;
#pragma unroll
    for (int c = 0; c < NCHUNK; c++) {
        wf[c] = __expf(mv[c] - M);
        denom += g_l[hq * NCHUNK + c] * wf[c];
    }
    float o = 0.0f;
#pragma unroll
    for (int c = 0; c < NCHUNK; c++)
        o += wf[c] * g_opart[(hq * NCHUNK + c) * HD + d];
    o /= denom;
    int h = hq / QL, q = hq % QL;
    g_ctx[q * HIDDEN + h * HD + d] = o;
}

// ---------------------------------------------------------------
extern "C" void kernel_launch(void* const* d_in, const int* in_sizes, int n_in,
                              void* d_out, int out_size)
{
    const int*   ipos  = (const int*)  d_in[0];
    const float* hs    = (const float*)d_in[1];
    const float* mask  = (const float*)d_in[2];
    const float* wpack = (const float*)d_in[3];
    const float* wo    = (const float*)d_in[4];
    const float* kc    = (const float*)d_in[5];
    const float* vc    = (const float*)d_in[6];
    float* out = (float*)d_out;

    const int smem = 3 * ROWS * 256 * 16;   // 48 KB dynamic, 0 static

    // 1) fused QKV projection -> g_q/g_k/g_v
    gemv8_kernel<<<(3 * HIDDEN) / ROWS, 256, smem>>>(hs, wpack, nullptr, 0);

    // 2) split-KV attention partials
    dim3 ag(NCHUNK, NH);
    attn_kernel<<<ag, 256>>>(kc, vc, mask, ipos);

    // 3) merge partials -> context
    combine_kernel<<<NH * QL, HD>>>();

    // 4) output projection -> d_out
    gemv8_kernel<<<HIDDEN / ROWS, 256, smem>>>(nullptr, wo, out, 1);
}

// round 8
// speedup vs baseline: 1.0732x; 1.0732x over previous
#include <cuda_runtime.h>
#include <math.h>
#include <float.h>

#define HIDDEN 5120
#define NH 40
#define HD 128
#define MAXL 2048
#define QL 8
#define CHUNK 256
#define NCHUNK (MAXL / CHUNK)
#define QK_SCALE 0.08838834764831845f  // 1/sqrt(128)
#define C4 (HIDDEN / 4)                // 1280 float4 per row
#define ROWS 4

// packed f32x2 FMA for attn kernel
#define FMAX2(acc, a, b) \
    asm("fma.rn.f32x2 %0, %1, %2, %0;" : "+l"(acc) : "l"(a), "l"(b))

__device__ __forceinline__ float x2lo(unsigned long long v) {
    return __uint_as_float((unsigned)(v & 0xffffffffu));
}
__device__ __forceinline__ float x2hi(unsigned long long v) {
    return __uint_as_float((unsigned)(v >> 32));
}
__device__ __forceinline__ float x2sum(unsigned long long v) {
    return x2lo(v) + x2hi(v);
}
__device__ __forceinline__ unsigned long long f32dup(float p) {
    unsigned b = __float_as_uint(p);
    return ((unsigned long long)b << 32) | b;
}

__device__ __forceinline__ unsigned smem_u32(const void* p) {
    unsigned a;
    asm("{ .reg .u64 t; cvta.to.shared.u64 t, %1; cvt.u32.u64 %0, t; }"
        : "=r"(a) : "l"(p));
    return a;
}

// ---------------- device scratch (no allocs allowed) ----------------
__device__ float g_q[NH * QL * HD];                    // [h][q][d], pre-scaled
__device__ float g_k[NH * QL * HD];                    // new K rows  [h][q][d]
__device__ float g_v[NH * QL * HD];                    // new V rows  [h][q][d]
__device__ float g_opart[NH * QL * NCHUNK * HD];       // [h][q][chunk][d]
__device__ float g_m[NH * QL * NCHUNK];                // chunk max
__device__ float g_l[NH * QL * NCHUNK];                // chunk expsum
__device__ float g_ctx[QL * HIDDEN];                   // attention out [q][h*128+d]

// ---------------------------------------------------------------
// Persistent GEMV, M=8: Y[q][r] = dot(X[q], W[r]).
// grid = #SMs, 1 CTA/SM. X (160 KB) preloaded into smem once per CTA;
// W streamed via 3-stage per-thread cp.async pipeline (48 KB).
// Each CTA grid-strides over row-groups of 4.
// TAIL FIX: when no real group is issued, commit an EMPTY group so the
// "two younger groups pending" invariant of wait_group 2 holds to the end.
// mode 0: W_pack -> g_q/g_k/g_v.  mode 1: W_o, X=g_ctx -> Y.
// Dynamic smem = 160K + 48K = 212992 B (opt-in via FuncSetAttribute).
// ---------------------------------------------------------------
__global__ void __launch_bounds__(256, 1) gemv_kernel(
    const float* __restrict__ Xin, const float* __restrict__ W,
    float* __restrict__ Y, int mode, int ngrp)
{
    extern __shared__ float smem[];
    float4* sX4 = reinterpret_cast<float4*>(smem);               // 160 KB
    float4* sW4 = reinterpret_cast<float4*>(smem + QL * HIDDEN); // 48 KB
    __shared__ float sred[8][32];

    int tid = threadIdx.x, bid = blockIdx.x, grid = gridDim.x;
    const float4* __restrict__ X4 =
        reinterpret_cast<const float4*>((mode == 1) ? g_ctx : Xin);

    // ---- X preload: one cp.async group of 40 x 16B per thread ----
    unsigned xsbase = smem_u32(sX4);
#pragma unroll
    for (int i = 0; i < (QL * C4) / 256; i++) {
        int idx = tid + i * 256;
        asm volatile("cp.async.cg.shared.global [%0], [%1], 16;"
                     :: "r"(xsbase + idx * 16), "l"(X4 + idx));
    }
    asm volatile("cp.async.commit_group;");

    unsigned sbase = smem_u32(sW4) + tid * 16;   // this thread's W slot
    int nloc = (ngrp - bid - 1) / grid + 1;      // groups owned by this CTA
    int total = nloc * 5;                        // logical iterations

    // issue logical iter idx (or empty commit if past end) into stage idx%3
    auto issue = [&](int idx) {
        if (idx < total) {
            int j = idx / 5, iti = idx - j * 5;
            int st = idx % 3;
            const float* g = W + ((size_t)(bid + j * grid) * ROWS) * HIDDEN
                               + iti * 1024 + tid * 4;
#pragma unroll
            for (int r = 0; r < ROWS; r++) {
                unsigned sa = sbase + (unsigned)((st * ROWS + r) << 12);
                asm volatile("cp.async.cg.shared.global [%0], [%1], 16;"
                             :: "r"(sa), "l"(g + (size_t)r * HIDDEN));
            }
        }
        asm volatile("cp.async.commit_group;");   // empty group if past end
    };

    issue(0); issue(1); issue(2);
    asm volatile("cp.async.wait_group 2;");      // X + iter0 complete
    __syncthreads();                              // X visible to all

    float acc[ROWS][QL];
#pragma unroll
    for (int r = 0; r < ROWS; r++)
#pragma unroll
        for (int q = 0; q < QL; q++) acc[r][q] = 0.0f;

    int lane = tid & 31, warp = tid >> 5;

    for (int n = 0; n < total; n++) {
        int j = n / 5, it = n - j * 5;
        int st = n % 3;
        if (n) asm volatile("cp.async.wait_group 2;");

        // consume W stage + X from smem
        float4 wv[ROWS];
#pragma unroll
        for (int r = 0; r < ROWS; r++) {
            unsigned sa = sbase + (unsigned)((st * ROWS + r) << 12);
            asm volatile("ld.shared.v4.f32 {%0,%1,%2,%3}, [%4];"
                         : "=f"(wv[r].x), "=f"(wv[r].y),
                           "=f"(wv[r].z), "=f"(wv[r].w) : "r"(sa));
        }
        int c4 = tid + it * 256;
#pragma unroll
        for (int q = 0; q < QL; q++) {
            float4 xv = sX4[q * C4 + c4];
#pragma unroll
            for (int r = 0; r < ROWS; r++) {
                acc[r][q] = fmaf(wv[r].x, xv.x, acc[r][q]);
                acc[r][q] = fmaf(wv[r].y, xv.y, acc[r][q]);
                acc[r][q] = fmaf(wv[r].z, xv.z, acc[r][q]);
                acc[r][q] = fmaf(wv[r].w, xv.w, acc[r][q]);
            }
        }

        issue(n + 3);   // real group or empty commit (keeps invariant)

        if (it == 4) {
            // ---- flush group j: reduce 32 accs across the block ----
            long r0 = (long)(bid + j * grid) * ROWS;
            __syncthreads();   // protect sred from prev group's readers
#pragma unroll
            for (int r = 0; r < ROWS; r++) {
#pragma unroll
                for (int q = 0; q < QL; q++) {
                    float v = acc[r][q];
                    v += __shfl_down_sync(0xffffffffu, v, 16);
                    v += __shfl_down_sync(0xffffffffu, v, 8);
                    v += __shfl_down_sync(0xffffffffu, v, 4);
                    v += __shfl_down_sync(0xffffffffu, v, 2);
                    v += __shfl_down_sync(0xffffffffu, v, 1);
                    if (lane == 0) sred[warp][r * QL + q] = v;
                    acc[r][q] = 0.0f;
                }
            }
            __syncthreads();
            if (tid < 32) {
                float v = 0.0f;
#pragma unroll
                for (int w = 0; w < 8; w++) v += sred[w][tid];
                long r = r0 + tid / QL;
                int q = tid % QL;
                if (mode == 0) {
                    int sect = (int)(r / HIDDEN);      // 0=q, 1=k, 2=v
                    int f = (int)(r % HIDDEN);
                    int h = f / HD, d = f % HD;
                    int o = (h * QL + q) * HD + d;
                    if (sect == 0)      g_q[o] = v * QK_SCALE;
                    else if (sect == 1) g_k[o] = v;
                    else                g_v[o] = v;
                } else {
                    Y[(long)q * HIDDEN + r] = v;
                }
            }
        }
    }
}

// ---------------------------------------------------------------
// Split-KV attention: block = (chunk of 256 keys, head). f32x2 in both
// matmul phases; probs stored pre-duplicated (p,p) in smem for PV phase.
// ---------------------------------------------------------------
__global__ void __launch_bounds__(256) attn_kernel(
    const float* __restrict__ kc, const float* __restrict__ vc,
    const float* __restrict__ mask, const int* __restrict__ ipos)
{
    int chunk = blockIdx.x;
    int h = blockIdx.y;
    int tid = threadIdx.x;
    int warp = tid >> 5, lane = tid & 31;

    __shared__ float qs[QL][HD];                    // 4 KB
    __shared__ float scf[QL][CHUNK];                // 8 KB scores
    __shared__ unsigned long long sc2[QL][CHUNK];   // 16 KB dup probs
    __shared__ float4 red[8][QL][32];               // 32 KB partial O
    __shared__ int pos[QL];
    __shared__ int sel[CHUNK];

    if (tid == 0) {
        bool is64 = (ipos[1] == 0);     // int64 little-endian high word
#pragma unroll
        for (int j = 0; j < QL; j++) pos[j] = is64 ? ipos[2 * j] : ipos[j];
    }
    for (int i = tid; i < QL * HD; i += 256) qs[0][i] = g_q[h * QL * HD + i];
    __syncthreads();

    // ---- scores: one key per thread, f32x2 pairs over d ----
    int key = chunk * CHUNK + tid;
    int s = -1;
#pragma unroll
    for (int j = 0; j < QL; j++) if (pos[j] == key) s = j;
    sel[tid] = s;

    const ulonglong2* kp = reinterpret_cast<const ulonglong2*>(
        (s >= 0) ? &g_k[(h * QL + s) * HD]
                 : &kc[((size_t)h * MAXL + key) * HD]);
    unsigned long long a2[QL];
#pragma unroll
    for (int q = 0; q < QL; q++) a2[q] = 0ull;
#pragma unroll
    for (int c = 0; c < HD / 4; c += 8) {
        ulonglong2 kv[8];
#pragma unroll
        for (int u = 0; u < 8; u++) kv[u] = __ldcg(kp + c + u);
#pragma unroll
        for (int u = 0; u < 8; u++) {
#pragma unroll
            for (int q = 0; q < QL; q++) {
                ulonglong2 qv = *reinterpret_cast<const ulonglong2*>(
                    &qs[q][(c + u) * 4]);
                FMAX2(a2[q], kv[u].x, qv.x);
                FMAX2(a2[q], kv[u].y, qv.y);
            }
        }
    }
#pragma unroll
    for (int q = 0; q < QL; q++) {
        float m = __ldcg(&mask[((size_t)h * MAXL + pos[q]) * MAXL + key]);
        scf[q][tid] = fmaxf(x2sum(a2[q]) + m, -FLT_MAX);
    }
    __syncthreads();

    // ---- softmax stats: warp q handles query q; write dup probs ----
    {
        float m = -FLT_MAX;
#pragma unroll
        for (int i = 0; i < CHUNK / 32; i++) m = fmaxf(m, scf[warp][lane + i * 32]);
#pragma unroll
        for (int o = 16; o > 0; o >>= 1) m = fmaxf(m, __shfl_xor_sync(0xffffffffu, m, o));
        float l = 0.0f;
#pragma unroll
        for (int i = 0; i < CHUNK / 32; i++) {
            float p = __expf(scf[warp][lane + i * 32] - m);
            sc2[warp][lane + i * 32] = f32dup(p);
            l += p;
        }
#pragma unroll
        for (int o = 16; o > 0; o >>= 1) l += __shfl_xor_sync(0xffffffffu, l, o);
        if (lane == 0) {
            g_m[(h * QL + warp) * NCHUNK + chunk] = m;
            g_l[(h * QL + warp) * NCHUNK + chunk] = l;
        }
    }
    __syncthreads();

    // ---- partial O = P^T V. warp w: keys w,w+8,...; lane: d-float4 ----
    unsigned long long acc[QL][2];     // 2 d-pairs per lane
#pragma unroll
    for (int q = 0; q < QL; q++) { acc[q][0] = 0ull; acc[q][1] = 0ull; }

#pragma unroll
    for (int j = 0; j < 32; j += 4) {
        ulonglong2 vv[4];
#pragma unroll
        for (int u = 0; u < 4; u++) {
            int k = warp + 8 * (j + u);
            int sv = sel[k];
            int kk = chunk * CHUNK + k;
            const ulonglong2* vp = reinterpret_cast<const ulonglong2*>(
                (sv >= 0) ? &g_v[(h * QL + sv) * HD]
                          : &vc[((size_t)h * MAXL + kk) * HD]);
            vv[u] = __ldcg(vp + lane);
        }
#pragma unroll
        for (int u = 0; u < 4; u++) {
            int k = warp + 8 * (j + u);
#pragma unroll
            for (int q = 0; q < QL; q++) {
                unsigned long long p2 = sc2[q][k];
                FMAX2(acc[q][0], p2, vv[u].x);
                FMAX2(acc[q][1], p2, vv[u].y);
            }
        }
    }
#pragma unroll
    for (int q = 0; q < QL; q++)
        red[warp][q][lane] = make_float4(x2lo(acc[q][0]), x2hi(acc[q][0]),
                                         x2lo(acc[q][1]), x2hi(acc[q][1]));
    __syncthreads();

    // reduce 8 warps: thread t handles (q, d4) = (t/32, t%32)
    {
        int q = tid >> 5, d4 = tid & 31;
        float4 o = red[0][q][d4];
#pragma unroll
        for (int w = 1; w < 8; w++) {
            float4 v = red[w][q][d4];
            o.x += v.x; o.y += v.y; o.z += v.z; o.w += v.w;
        }
        reinterpret_cast<float4*>(
            &g_opart[((h * QL + q) * NCHUNK + chunk) * HD])[d4] = o;
    }
}

// ---------------------------------------------------------------
// Combine split-KV partials (log-sum-exp merge) -> context [q][h*128+d]
// ---------------------------------------------------------------
__global__ void __launch_bounds__(HD) combine_kernel()
{
    int hq = blockIdx.x;                // h*QL + q
    int d = threadIdx.x;
    float mv[NCHUNK];
    float M = -FLT_MAX;
#pragma unroll
    for (int c = 0; c < NCHUNK; c++) {
        mv[c] = g_m[hq * NCHUNK + c];
        M = fmaxf(M, mv[c]);
    }
    float wf[NCHUNK];
    float denom = 0.0f;
#pragma unroll
    for (int c = 0; c < NCHUNK; c++) {
        wf[c] = __expf(mv[c] - M);
        denom += g_l[hq * NCHUNK + c] * wf[c];
    }
    float o = 0.0f;
#pragma unroll
    for (int c = 0; c < NCHUNK; c++)
        o += wf[c] * g_opart[(hq * NCHUNK + c) * HD + d];
    o /= denom;
    int h = hq / QL, q = hq % QL;
    g_ctx[q * HIDDEN + h * HD + d] = o;
}

// ---------------------------------------------------------------
extern "C" void kernel_launch(void* const* d_in, const int* in_sizes, int n_in,
                              void* d_out, int out_size)
{
    const int*   ipos  = (const int*)  d_in[0];
    const float* hs    = (const float*)d_in[1];
    const float* mask  = (const float*)d_in[2];
    const float* wpack = (const float*)d_in[3];
    const float* wo    = (const float*)d_in[4];
    const float* kc    = (const float*)d_in[5];
    const float* vc    = (const float*)d_in[6];
    float* out = (float*)d_out;

    const int smem = QL * HIDDEN * 4 + 3 * ROWS * 256 * 16;   // 212992 B
    cudaFuncSetAttribute(gemv_kernel,
                         cudaFuncAttributeMaxDynamicSharedMemorySize, smem);

    int nsm = 148;
    cudaDeviceGetAttribute(&nsm, cudaDevAttrMultiProcessorCount, 0);

    // 1) fused QKV projection -> g_q/g_k/g_v  (3840 row-groups)
    gemv_kernel<<<nsm, 256, smem>>>(hs, wpack, nullptr, 0,
                                    (3 * HIDDEN) / ROWS);

    // 2) split-KV attention partials
    dim3 ag(NCHUNK, NH);
    attn_kernel<<<ag, 256>>>(kc, vc, mask, ipos);

    // 3) merge partials -> context
    combine_kernel<<<NH * QL, HD>>>();

    // 4) output projection -> d_out  (1280 row-groups)
    gemv_kernel<<<nsm, 256, smem>>>(nullptr, wo, out, 1, HIDDEN / ROWS);
}